// round 13
// baseline (speedup 1.0000x reference)
#include <cuda_runtime.h>
#include <cuda_fp16.h>
#include <cuda_bf16.h>

#define NN 50000
#define EE 800000
#define FI 128
#define HH 128
#define GG 256
#define TT 4

#define SCAN_BLKS 49   // 12500 int4 / 256

// ---------------- streams/events (created once at program init) ----------------
struct SideStream {
    cudaStream_t s2;
    cudaEvent_t  evFork, evDinv, evCsr;
    SideStream() {
        cudaStreamCreateWithFlags(&s2, cudaStreamNonBlocking);
        cudaEventCreateWithFlags(&evFork, cudaEventDisableTiming);
        cudaEventCreateWithFlags(&evDinv, cudaEventDisableTiming);
        cudaEventCreateWithFlags(&evCsr,  cudaEventDisableTiming);
    }
};
static SideStream g_ss;

// ---------------- scratch (device globals) ----------------
__device__ int    g_deg[NN];
__device__ int    g_rowptr[NN + 1];
__device__ int    g_pos[NN];
__device__ int    g_col[EE];
__device__ float  g_dinv[NN];
__device__ int    g_blk_agg[SCAN_BLKS];
__device__ int    g_blk_pfx[SCAN_BLKS];
__device__ int    g_blk_stat[SCAN_BLKS];   // 0 none, 1 agg ready, 2 prefix ready
__device__ uint2  g_tsh[NN * 32];    // ts = dinv*(X@W) fp16, 4 halves/uint2 (16B-aligned via uint4 view? see note)
__device__ float4 g_h[NN * 32];      // layer activations (fp32)
__device__ unsigned long long g_Wp1[64 * 128];  // W packed as (W[2t][c], W[2t+1][c])
__device__ unsigned long long g_Wp2[64 * 128];

__device__ __forceinline__ void ffma2(unsigned long long& d, unsigned long long a,
                                      unsigned long long b) {
    asm("fma.rn.f32x2 %0, %1, %2, %0;" : "+l"(d) : "l"(a), "l"(b));
}

// ---------------- init: zero deg + scan statuses + rowptr[NN] + pack W1/W2 ----------------
__global__ void k_init(const float* __restrict__ W1, const float* __restrict__ W2) {
    int idx = blockIdx.x * blockDim.x + threadIdx.x;   // 64 blocks x 256 = 16384
    if (idx < NN / 4) ((int4*)g_deg)[idx] = make_int4(0, 0, 0, 0);
    if (idx < SCAN_BLKS) g_blk_stat[idx] = 0;
    if (idx == 0) g_rowptr[NN] = EE;
    int half = idx >> 13;
    int j = idx & 8191;
    int t = j >> 7;
    int c = j & 127;
    const float* W = half ? W2 : W1;
    unsigned lo = __float_as_uint(W[(2 * t) * 128 + c]);
    unsigned hi = __float_as_uint(W[(2 * t + 1) * 128 + c]);
    unsigned long long v = ((unsigned long long)hi << 32) | lo;
    if (half) g_Wp2[j] = v; else g_Wp1[j] = v;
}

// ---------------- degree histogram (edge_index is int32) ----------------
__global__ void k_hist(const int* __restrict__ ei) {
    int e4 = blockIdx.x * blockDim.x + threadIdx.x;
    if (e4 < EE / 4) {
        int4 d = ((const int4*)(ei + EE))[e4];
        atomicAdd(&g_deg[d.x], 1);
        atomicAdd(&g_deg[d.y], 1);
        atomicAdd(&g_deg[d.z], 1);
        atomicAdd(&g_deg[d.w], 1);
    }
}

// ---------------- single-pass scan with decoupled lookback (49 blocks) ----------------
__global__ void k_scan() {
    __shared__ int ws[8];
    __shared__ int sh_off;
    __shared__ int sh_bt;
    int tid = threadIdx.x, lane = tid & 31, wid = tid >> 5;
    int i4 = blockIdx.x * 256 + tid;
    int4 d = make_int4(0, 0, 0, 0);
    if (i4 < NN / 4) d = ((const int4*)g_deg)[i4];
    int tot = d.x + d.y + d.z + d.w;
    int incl = tot;
    #pragma unroll
    for (int o = 1; o < 32; o <<= 1) {
        int t = __shfl_up_sync(0xffffffffu, incl, o);
        if (lane >= o) incl += t;
    }
    if (lane == 31) ws[wid] = incl;
    __syncthreads();
    if (wid == 0) {
        int s = (lane < 8) ? ws[lane] : 0;
        int si = s;
        #pragma unroll
        for (int o = 1; o < 8; o <<= 1) {
            int t = __shfl_up_sync(0xffffffffu, si, o);
            if (lane >= o) si += t;
        }
        if (lane < 8) ws[lane] = si - s;
    }
    __syncthreads();
    int excl_in_blk = ws[wid] + incl - tot;
    if (tid == 255) sh_bt = excl_in_blk + tot;
    __syncthreads();
    int bt = sh_bt;

    if (tid == 0) {
        if (blockIdx.x == 0) {
            g_blk_pfx[0] = bt;
            __threadfence();
            atomicExch(&g_blk_stat[0], 2);
            sh_off = 0;
        } else {
            g_blk_agg[blockIdx.x] = bt;
            __threadfence();
            atomicExch(&g_blk_stat[blockIdx.x], 1);
            volatile int* vagg = (volatile int*)g_blk_agg;
            volatile int* vpfx = (volatile int*)g_blk_pfx;
            int running = 0;
            for (int j = (int)blockIdx.x - 1; j >= 0; ) {
                int s;
                do { s = atomicAdd(&g_blk_stat[j], 0); } while (s == 0);
                if (s == 2) { running += vpfx[j]; break; }
                running += vagg[j];
                j--;
            }
            sh_off = running;
            g_blk_pfx[blockIdx.x] = running + bt;
            __threadfence();
            atomicExch(&g_blk_stat[blockIdx.x], 2);
        }
    }
    __syncthreads();
    int run = sh_off + excl_in_blk;
    if (i4 < NN / 4) {
        int p0 = run, p1 = p0 + d.x, p2 = p1 + d.y, p3 = p2 + d.z;
        ((int4*)g_rowptr)[i4] = make_int4(p0, p1, p2, p3);
        ((int4*)g_pos)[i4]    = make_int4(p0, p1, p2, p3);
        float4 dv;
        dv.x = rsqrtf((float)(d.x + 1));
        dv.y = rsqrtf((float)(d.y + 1));
        dv.z = rsqrtf((float)(d.z + 1));
        dv.w = rsqrtf((float)(d.w + 1));
        ((float4*)g_dinv)[i4] = dv;
    }
}

__global__ void k_fill(const int* __restrict__ ei) {
    int e4 = blockIdx.x * blockDim.x + threadIdx.x;
    if (e4 < EE / 4) {
        int4 d = ((const int4*)(ei + EE))[e4];
        int4 s = ((const int4*)ei)[e4];
        int p;
        p = atomicAdd(&g_pos[d.x], 1); g_col[p] = s.x;
        p = atomicAdd(&g_pos[d.y], 1); g_col[p] = s.y;
        p = atomicAdd(&g_pos[d.z], 1); g_col[p] = s.z;
        p = atomicAdd(&g_pos[d.w], 1); g_col[p] = s.w;
    }
}

// ---------------- GEMM (FFMA2): g_tsh = fp16( dinv[i] * (X[i,:] @ W) ) ----------------
template <int SEL>
__global__ void k_gemm(const float4* __restrict__ Xin) {
    __shared__ float4 Xs4[64 * 32];
    const float4* X4 = SEL ? (const float4*)g_h : Xin;
    const ulonglong2* Wp2 = (const ulonglong2*)(SEL ? g_Wp2 : g_Wp1);
    int tid  = threadIdx.x;
    int row0 = blockIdx.x * 64;

    #pragma unroll
    for (int j = 0; j < 8; j++) {
        int fi = tid + j * 256;
        int r  = fi >> 5;
        int kq = fi & 31;
        int gr = row0 + r;
        float4 v = make_float4(0.f, 0.f, 0.f, 0.f);
        if (gr < NN) v = X4[gr * 32 + kq];
        Xs4[fi] = v;
    }
    __syncthreads();

    int tx = tid & 31;
    int ty = tid >> 5;
    unsigned long long acc2[8][4];
    #pragma unroll
    for (int i = 0; i < 8; i++)
        #pragma unroll
        for (int c = 0; c < 4; c++) acc2[i][c] = 0ull;

    const unsigned long long* Xs64 = (const unsigned long long*)Xs4;
    #pragma unroll 4
    for (int t = 0; t < 64; t++) {
        ulonglong2 wa = Wp2[t * 64 + 2 * tx];
        ulonglong2 wb = Wp2[t * 64 + 2 * tx + 1];
        #pragma unroll
        for (int i = 0; i < 8; i++) {
            unsigned long long xp = Xs64[(ty * 8 + i) * 64 + t];
            ffma2(acc2[i][0], xp, wa.x);
            ffma2(acc2[i][1], xp, wa.y);
            ffma2(acc2[i][2], xp, wb.x);
            ffma2(acc2[i][3], xp, wb.y);
        }
    }

    #pragma unroll
    for (int i = 0; i < 8; i++) {
        int gr = row0 + ty * 8 + i;
        if (gr < NN) {
            float di = g_dinv[gr];
            float r[4];
            #pragma unroll
            for (int c = 0; c < 4; c++) {
                unsigned long long v = acc2[i][c];
                r[c] = (__uint_as_float((unsigned)v) + __uint_as_float((unsigned)(v >> 32))) * di;
            }
            __half2 ha = __floats2half2_rn(r[0], r[1]);
            __half2 hb = __floats2half2_rn(r[2], r[3]);
            uint2 o;
            o.x = *reinterpret_cast<unsigned*>(&ha);
            o.y = *reinterpret_cast<unsigned*>(&hb);
            g_tsh[gr * 32 + tx] = o;
        }
    }
}

// ---------------- aggregation: paired-edge gather, one warp per node ----------------
// lanes 0-15 fetch edge j (uint4 = 8 features each), lanes 16-31 fetch edge j+1.
// acc holds 8 features per lane; halves combined via shfl_xor(16) at the end.
__device__ __forceinline__ void acc_u4(float2& a0, float2& a1, float2& a2, float2& a3,
                                       uint4 u) {
    __half2* hp = (__half2*)&u;
    float2 f0 = __half22float2(hp[0]);
    float2 f1 = __half22float2(hp[1]);
    float2 f2 = __half22float2(hp[2]);
    float2 f3 = __half22float2(hp[3]);
    a0.x += f0.x; a0.y += f0.y;
    a1.x += f1.x; a1.y += f1.y;
    a2.x += f2.x; a2.y += f2.y;
    a3.x += f3.x; a3.y += f3.y;
}

__global__ void k_agg(const float4* __restrict__ b4) {
    int gtid = blockIdx.x * blockDim.x + threadIdx.x;
    int node = gtid >> 5;
    int lane = threadIdx.x & 31;
    if (node >= NN) return;
    int half = lane >> 4, li = lane & 15;
    const uint4* ts16 = (const uint4*)g_tsh;   // 16 uint4 per node (128 fp16)

    float2 a0 = make_float2(0.f, 0.f), a1 = a0, a2 = a0, a3 = a0;

    // self term (ts already dinv-scaled): half 0 only
    if (half == 0) {
        uint4 u = ts16[node * 16 + li];
        acc_u4(a0, a1, a2, a3, u);
    }

    int s = g_rowptr[node];
    int cnt = g_rowptr[node + 1] - s;
    int k = half;
    // 2 gathers in flight per iteration = 4 edges
    for (; k + 2 < cnt; k += 4) {
        int c0 = g_col[s + k];
        int c1 = g_col[s + k + 2];
        uint4 u0 = ts16[c0 * 16 + li];
        uint4 u1 = ts16[c1 * 16 + li];
        acc_u4(a0, a1, a2, a3, u0);
        acc_u4(a0, a1, a2, a3, u1);
    }
    for (; k < cnt; k += 2) {
        int c = g_col[s + k];
        uint4 u = ts16[c * 16 + li];
        acc_u4(a0, a1, a2, a3, u);
    }

    // combine the two halves
    a0.x += __shfl_xor_sync(0xffffffffu, a0.x, 16);
    a0.y += __shfl_xor_sync(0xffffffffu, a0.y, 16);
    a1.x += __shfl_xor_sync(0xffffffffu, a1.x, 16);
    a1.y += __shfl_xor_sync(0xffffffffu, a1.y, 16);
    a2.x += __shfl_xor_sync(0xffffffffu, a2.x, 16);
    a2.y += __shfl_xor_sync(0xffffffffu, a2.y, 16);
    a3.x += __shfl_xor_sync(0xffffffffu, a3.x, 16);
    a3.y += __shfl_xor_sync(0xffffffffu, a3.y, 16);

    if (half == 0) {
        float di = g_dinv[node];
        float4 bb0 = b4[li * 2];
        float4 bb1 = b4[li * 2 + 1];
        float4 o0, o1;
        o0.x = fmaxf(fmaf(a0.x, di, bb0.x), 0.f);
        o0.y = fmaxf(fmaf(a0.y, di, bb0.y), 0.f);
        o0.z = fmaxf(fmaf(a1.x, di, bb0.z), 0.f);
        o0.w = fmaxf(fmaf(a1.y, di, bb0.w), 0.f);
        o1.x = fmaxf(fmaf(a2.x, di, bb1.x), 0.f);
        o1.y = fmaxf(fmaf(a2.y, di, bb1.y), 0.f);
        o1.z = fmaxf(fmaf(a3.x, di, bb1.z), 0.f);
        o1.w = fmaxf(fmaf(a3.y, di, bb1.w), 0.f);
        g_h[node * 32 + li * 2]     = o0;
        g_h[node * 32 + li * 2 + 1] = o1;
    }
}

// ---------------- fused mean-pool + FC + head ----------------
__device__ __forceinline__ int lb_batch(const int* b, int v) {
    int lo = 0, hi = NN;
    while (lo < hi) {
        int m = (lo + hi) >> 1;
        if (b[m] < v) lo = m + 1; else hi = m;
    }
    return lo;
}

__global__ void k_poolhead(const int* __restrict__ batch,
                           const float* __restrict__ Wfc, const float* __restrict__ bfc,
                           const float* __restrict__ Wh, const float* __restrict__ bh,
                           float* __restrict__ out) {
    int g = blockIdx.x;
    int tid = threadIdx.x;   // 0..127
    __shared__ int s0, s1;
    __shared__ float pr[128];
    __shared__ float zs[128];
    if (tid == 0) {
        s0 = lb_batch(batch, g);
        s1 = lb_batch(batch, g + 1);
    }
    __syncthreads();
    int a = s0, bnd = s1;
    const float* h = (const float*)g_h;
    float acc = 0.f;
    int n = a;
    for (; n + 3 < bnd; n += 4) {
        acc += h[n * 128 + tid] + h[(n + 1) * 128 + tid]
             + h[(n + 2) * 128 + tid] + h[(n + 3) * 128 + tid];
    }
    for (; n < bnd; n++) acc += h[n * 128 + tid];
    float cnt = (float)(bnd - a);
    pr[tid] = acc / fmaxf(cnt, 1.f);
    __syncthreads();
    float z = bfc[tid];
    #pragma unroll 4
    for (int k = 0; k < 128; k++) z = fmaf(pr[k], Wfc[k * 128 + tid], z);
    zs[tid] = fmaxf(z, 0.f);
    __syncthreads();
    if (tid < TT * 2) {
        int t = tid >> 1, c = tid & 1;
        float s = bh[t * 2 + c];
        #pragma unroll 4
        for (int k = 0; k < 128; k++) s = fmaf(zs[k], Wh[t * 256 + k * 2 + c], s);
        out[t * (GG * 2) + g * 2 + c] = s;
    }
}

// ---------------- launch: fork-join (gemm1 waits on dinv, overlaps fill) ----------------
extern "C" void kernel_launch(void* const* d_in, const int* in_sizes, int n_in,
                              void* d_out, int out_size) {
    const float* x     = (const float*)d_in[0];
    const int*   ei    = (const int*)d_in[1];
    const int*   batch = (const int*)d_in[2];
    const float* W1    = (const float*)d_in[3];
    const float* b1    = (const float*)d_in[4];
    const float* W2    = (const float*)d_in[5];
    const float* b2    = (const float*)d_in[6];
    const float* Wfc   = (const float*)d_in[7];
    const float* bfc   = (const float*)d_in[8];
    const float* Wh    = (const float*)d_in[9];
    const float* bh    = (const float*)d_in[10];
    float* out = (float*)d_out;

    cudaStream_t s2 = g_ss.s2;

    // init (zero deg, statuses, pack weights) on main stream
    k_init<<<64, 256>>>(W1, W2);

    // fork: CSR pipeline on side stream
    cudaEventRecord(g_ss.evFork, 0);
    cudaStreamWaitEvent(s2, g_ss.evFork, 0);

    k_hist<<<(EE / 4 + 255) / 256, 256, 0, s2>>>(ei);
    k_scan<<<SCAN_BLKS, 256, 0, s2>>>();
    cudaEventRecord(g_ss.evDinv, s2);          // dinv/rowptr ready
    k_fill<<<(EE / 4 + 255) / 256, 256, 0, s2>>>(ei);
    cudaEventRecord(g_ss.evCsr, s2);           // col ready

    int tile_blocks = (NN + 63) / 64;
    int agg_blocks  = (NN * 32 + 255) / 256;

    // main: GEMM1 needs dinv only — overlaps k_fill
    cudaStreamWaitEvent(0, g_ss.evDinv, 0);
    k_gemm<0><<<tile_blocks, 256>>>((const float4*)x);

    // join: aggregation needs col list too
    cudaStreamWaitEvent(0, g_ss.evCsr, 0);
    k_agg<<<agg_blocks, 256>>>((const float4*)b1);
    k_gemm<1><<<tile_blocks, 256>>>((const float4*)x);
    k_agg<<<agg_blocks, 256>>>((const float4*)b2);
    k_poolhead<<<GG, 128>>>(batch, Wfc, bfc, Wh, bh, out);
}